// round 4
// baseline (speedup 1.0000x reference)
#include <cuda_runtime.h>
#include <math.h>

// Problem constants
#define B_   8192
#define D_   2048
#define K_   256
#define ALPHA_ 1000.0f

// Scratch (no cudaMalloc allowed): emb [B,K] fp32 = 8 MB, row norms.
__device__ float g_emb[B_ * K_];
__device__ float g_enorm[B_];
__device__ float g_cnorm[K_];

// ---------------------------------------------------------------------------
// Generic fp32 SGEMM: C[M,N] = A[M,K] @ B[K,N] + bias[N]
// All row-major. BM=128, BN=128, BK=8, TM=8, TN=8, 256 threads.
// ---------------------------------------------------------------------------
template <int BM, int BN, int BK, int TM, int TN>
__global__ __launch_bounds__(256) void sgemm_bias(
    int M, int N, int Kd,
    const float* __restrict__ A, const float* __restrict__ Bm,
    const float* __restrict__ bias, float* __restrict__ C)
{
    __shared__ float As[BK][BM];   // A tile, transposed (K-major -> M contiguous)
    __shared__ float Bs[BK][BN];

    const int tid  = threadIdx.x;
    const int tCol = tid % (BN / TN);   // 0..15
    const int tRow = tid / (BN / TN);   // 0..15

    const float* Ag = A + (size_t)blockIdx.y * BM * Kd;
    const float* Bg = Bm + (size_t)blockIdx.x * BN;

    float acc[TM][TN];
#pragma unroll
    for (int i = 0; i < TM; i++)
#pragma unroll
        for (int j = 0; j < TN; j++) acc[i][j] = 0.0f;

    // Load mapping: one float4 per thread per tile.
    const int aRow = tid / (BK / 4);     // 0..127
    const int aCol = tid % (BK / 4);     // 0..1
    const int bRow = tid / (BN / 4);     // 0..7
    const int bCol = tid % (BN / 4);     // 0..31

    for (int k0 = 0; k0 < Kd; k0 += BK) {
        float4 av = *(const float4*)(Ag + (size_t)aRow * Kd + k0 + aCol * 4);
        As[aCol * 4 + 0][aRow] = av.x;
        As[aCol * 4 + 1][aRow] = av.y;
        As[aCol * 4 + 2][aRow] = av.z;
        As[aCol * 4 + 3][aRow] = av.w;
        *(float4*)&Bs[bRow][bCol * 4] =
            *(const float4*)(Bg + (size_t)(k0 + bRow) * N + bCol * 4);
        __syncthreads();

#pragma unroll
        for (int kk = 0; kk < BK; kk++) {
            float ra[TM], rb[TN];
#pragma unroll
            for (int i = 0; i < TM; i++) ra[i] = As[kk][tRow * TM + i];
#pragma unroll
            for (int j = 0; j < TN; j++) rb[j] = Bs[kk][tCol * TN + j];
#pragma unroll
            for (int i = 0; i < TM; i++)
#pragma unroll
                for (int j = 0; j < TN; j++)
                    acc[i][j] = fmaf(ra[i], rb[j], acc[i][j]);
        }
        __syncthreads();
    }

    // Epilogue: add bias, vectorized stores
#pragma unroll
    for (int i = 0; i < TM; i++) {
        const int row = blockIdx.y * BM + tRow * TM + i;
#pragma unroll
        for (int j = 0; j < TN; j += 4) {
            const int col = blockIdx.x * BN + tCol * TN + j;
            float4 bv = *(const float4*)(bias + col);
            float4 o;
            o.x = acc[i][j + 0] + bv.x;
            o.y = acc[i][j + 1] + bv.y;
            o.z = acc[i][j + 2] + bv.z;
            o.w = acc[i][j + 3] + bv.w;
            *(float4*)(C + (size_t)row * N + col) = o;
        }
    }
}

// ---------------------------------------------------------------------------
// Row-wise squared norms for a [rows, 256] fp32 matrix. One warp per row.
// ---------------------------------------------------------------------------
__global__ void rownorm256(const float* __restrict__ src, float* __restrict__ dst,
                           int rows)
{
    const int gw   = (blockIdx.x * blockDim.x + threadIdx.x) >> 5;
    const int lane = threadIdx.x & 31;
    if (gw >= rows) return;
    const float4* p = (const float4*)(src + (size_t)gw * 256);
    float4 a = p[lane];
    float4 b = p[lane + 32];
    float s = a.x * a.x + a.y * a.y + a.z * a.z + a.w * a.w
            + b.x * b.x + b.y * b.y + b.z * b.z + b.w * b.w;
#pragma unroll
    for (int o = 16; o > 0; o >>= 1) s += __shfl_xor_sync(0xffffffffu, s, o);
    if (lane == 0) dst[gw] = s;
}

// ---------------------------------------------------------------------------
// Fused dist + stable softmin + weighted_dist (transposed [K,B] output).
// Block: 64 rows of emb x all 256 clusters. 256 threads = 8 warps.
// Warp w owns rows w*8..w*8+7 fully: lane holds 8 cluster columns (lane+32c),
// so per-row min/sum are pure warp shuffles.
// ---------------------------------------------------------------------------
__global__ __launch_bounds__(256) void kmeans_softmin(
    const float* __restrict__ emb, const float* __restrict__ CR,
    const float* __restrict__ enorm, const float* __restrict__ cnorm,
    float* __restrict__ outWD)
{
    __shared__ float Es[32][65];    // emb tile [j][row], padded (store conflicts)
    __shared__ float Cs[32][257];   // CR  tile [j][k],  padded

    const int tid  = threadIdx.x;
    const int lane = tid & 31;
    const int wid  = tid >> 5;         // 0..7
    const int b0   = blockIdx.x * 64;

    float acc[8][8];
#pragma unroll
    for (int i = 0; i < 8; i++)
#pragma unroll
        for (int c = 0; c < 8; c++) acc[i][c] = 0.0f;

    for (int j0 = 0; j0 < 256; j0 += 32) {
        // emb tile: 64 rows x 32 cols = 512 float4, 2 per thread
#pragma unroll
        for (int t = 0; t < 2; t++) {
            const int idx = tid + t * 256;       // 0..511
            const int r   = idx >> 3;            // 8 float4 per row
            const int c4  = idx & 7;
            float4 v = *(const float4*)(emb + (size_t)(b0 + r) * 256 + j0 + c4 * 4);
            Es[c4 * 4 + 0][r] = v.x;
            Es[c4 * 4 + 1][r] = v.y;
            Es[c4 * 4 + 2][r] = v.z;
            Es[c4 * 4 + 3][r] = v.w;
        }
        // CR tile: 256 rows x 32 cols = 2048 float4, 8 per thread
#pragma unroll
        for (int t = 0; t < 8; t++) {
            const int idx = tid + t * 256;       // 0..2047
            const int k   = idx >> 3;
            const int c4  = idx & 7;
            float4 v = *(const float4*)(CR + (size_t)k * 256 + j0 + c4 * 4);
            Cs[c4 * 4 + 0][k] = v.x;
            Cs[c4 * 4 + 1][k] = v.y;
            Cs[c4 * 4 + 2][k] = v.z;
            Cs[c4 * 4 + 3][k] = v.w;
        }
        __syncthreads();

#pragma unroll 8
        for (int kk = 0; kk < 32; kk++) {
            float ra[8], rb[8];
#pragma unroll
            for (int i = 0; i < 8; i++) ra[i] = Es[kk][wid * 8 + i];
#pragma unroll
            for (int c = 0; c < 8; c++) rb[c] = Cs[kk][lane + 32 * c];
#pragma unroll
            for (int i = 0; i < 8; i++)
#pragma unroll
                for (int c = 0; c < 8; c++)
                    acc[i][c] = fmaf(ra[i], rb[c], acc[i][c]);
        }
        __syncthreads();
    }

    float cn[8];
#pragma unroll
    for (int c = 0; c < 8; c++) cn[c] = cnorm[lane + 32 * c];

#pragma unroll
    for (int i = 0; i < 8; i++) {
        const int b = b0 + wid * 8 + i;
        const float en = enorm[b];
        float d[8];
        float m = INFINITY;
#pragma unroll
        for (int c = 0; c < 8; c++) {
            d[c] = en - 2.0f * acc[i][c] + cn[c];
            m = fminf(m, d[c]);
        }
#pragma unroll
        for (int o = 16; o > 0; o >>= 1)
            m = fminf(m, __shfl_xor_sync(0xffffffffu, m, o));

        float e[8];
        float s = 0.0f;
#pragma unroll
        for (int c = 0; c < 8; c++) {
            e[c] = expf(-ALPHA_ * (d[c] - m));
            s += e[c];
        }
#pragma unroll
        for (int o = 16; o > 0; o >>= 1)
            s += __shfl_xor_sync(0xffffffffu, s, o);
        const float inv = 1.0f / s;

#pragma unroll
        for (int c = 0; c < 8; c++) {
            const int k = lane + 32 * c;
            outWD[(size_t)k * B_ + b] = d[c] * e[c] * inv;
        }
    }
}

// ---------------------------------------------------------------------------
// Launch: emb GEMM -> norms -> recon GEMM -> fused dist/softmin.
// Output layout: [ weighted_dist (K_*B_) | reconstruction (B_*D_) ].
// ---------------------------------------------------------------------------
extern "C" void kernel_launch(void* const* d_in, const int* in_sizes, int n_in,
                              void* d_out, int out_size)
{
    const float* x     = (const float*)d_in[0];  // [B, D]
    const float* W_enc = (const float*)d_in[1];  // [D, K]
    const float* b_enc = (const float*)d_in[2];  // [K]
    const float* W_dec = (const float*)d_in[3];  // [K, D]
    const float* b_dec = (const float*)d_in[4];  // [D]
    const float* CR    = (const float*)d_in[5];  // [K, K]

    float* out    = (float*)d_out;
    float* outWD  = out;                         // [K, B]
    float* outRec = out + (size_t)K_ * B_;       // [B, D]

    float* emb = nullptr;
    float* en  = nullptr;
    float* cn  = nullptr;
    cudaGetSymbolAddress((void**)&emb, g_emb);
    cudaGetSymbolAddress((void**)&en,  g_enorm);
    cudaGetSymbolAddress((void**)&cn,  g_cnorm);

    // 1) emb = x @ W_enc + b_enc   [8192, 256]
    sgemm_bias<128, 128, 8, 8, 8>
        <<<dim3(K_ / 128, B_ / 128), 256>>>(B_, K_, D_, x, W_enc, b_enc, emb);

    // 2) row norms: ||emb_b||^2 and ||c_k||^2
    rownorm256<<<B_ / 8, 256>>>(emb, en, B_);
    rownorm256<<<K_ / 8, 256>>>(CR, cn, K_);

    // 3) reconstruction = emb @ W_dec + b_dec   [8192, 2048]
    sgemm_bias<128, 128, 8, 8, 8>
        <<<dim3(D_ / 128, B_ / 128), 256>>>(B_, D_, K_, emb, W_dec, b_dec, outRec);

    // 4) dist + softmin + weighted_dist (transposed write)
    kmeans_softmin<<<B_ / 64, 256>>>(emb, CR, en, cn, outWD);
}

// round 10
// speedup vs baseline: 1.5256x; 1.5256x over previous
#include <cuda_runtime.h>
#include <cuda_fp16.h>
#include <cstdint>
#include <math.h>

#define B_   8192
#define D_   2048
#define K_   256
#define ALPHA_ 1000.0f

// ---------------------------------------------------------------------------
// Device scratch (no cudaMalloc allowed)
// ---------------------------------------------------------------------------
__device__ float g_emb[B_ * K_];
__device__ float g_enorm[B_];
__device__ float g_cnorm[K_];
// fp16 2-level splits
__device__ __half g_xh[B_ * D_];    // x
__device__ __half g_xl[B_ * D_];
__device__ __half g_weh[K_ * D_];   // W_enc^T * 64
__device__ __half g_wel[K_ * D_];
__device__ __half g_wdh[D_ * K_];   // W_dec^T * 16
__device__ __half g_wdl[D_ * K_];
__device__ __half g_eh[B_ * K_];    // emb
__device__ __half g_el[B_ * K_];

// ---------------------------------------------------------------------------
// Helpers
// ---------------------------------------------------------------------------
__device__ __forceinline__ uint32_t smem_u32(const void* p) {
    uint32_t a;
    asm("{ .reg .u64 t; cvta.to.shared.u64 t, %1; cvt.u32.u64 %0, t; }"
        : "=r"(a) : "l"(p));
    return a;
}

__device__ __forceinline__ void cp_async16(uint32_t dst, const void* src) {
    asm volatile("cp.async.cg.shared.global [%0], [%1], 16;"
                 :: "r"(dst), "l"(src) : "memory");
}
#define CP_COMMIT() asm volatile("cp.async.commit_group;" ::: "memory")
#define CP_WAIT(N)  asm volatile("cp.async.wait_group %0;" :: "n"(N) : "memory")

__device__ __forceinline__ void ldm_x4(uint32_t* r, uint32_t addr) {
    asm volatile("ldmatrix.sync.aligned.m8n8.x4.shared.b16 {%0,%1,%2,%3}, [%4];"
                 : "=r"(r[0]), "=r"(r[1]), "=r"(r[2]), "=r"(r[3]) : "r"(addr));
}

__device__ __forceinline__ void mma16816(float* c, const uint32_t* a,
                                         uint32_t b0, uint32_t b1) {
    asm volatile(
        "mma.sync.aligned.m16n8k16.row.col.f32.f16.f16.f32 "
        "{%0,%1,%2,%3}, {%4,%5,%6,%7}, {%8,%9}, {%0,%1,%2,%3};"
        : "+f"(c[0]), "+f"(c[1]), "+f"(c[2]), "+f"(c[3])
        : "r"(a[0]), "r"(a[1]), "r"(a[2]), "r"(a[3]), "r"(b0), "r"(b1));
}

// ---------------------------------------------------------------------------
// Split kernels (fp16 2-level): v = h + l with h = fp16(v), l = fp16(v - h)
// ---------------------------------------------------------------------------
__global__ __launch_bounds__(256) void split2h(
    const float* __restrict__ in, __half* __restrict__ h,
    __half* __restrict__ l, int n4)
{
    int i = blockIdx.x * 256 + threadIdx.x;
    if (i >= n4) return;
    float4 v = ((const float4*)in)[i];
    float vv[4] = {v.x, v.y, v.z, v.w};
    __half hh[4], ll[4];
#pragma unroll
    for (int j = 0; j < 4; j++) {
        hh[j] = __float2half_rn(vv[j]);
        ll[j] = __float2half_rn(vv[j] - __half2float(hh[j]));
    }
    __half2* H = (__half2*)h;
    __half2* L = (__half2*)l;
    H[2 * i]     = __halves2half2(hh[0], hh[1]);
    H[2 * i + 1] = __halves2half2(hh[2], hh[3]);
    L[2 * i]     = __halves2half2(ll[0], ll[1]);
    L[2 * i + 1] = __halves2half2(ll[2], ll[3]);
}

// Transpose + scale + split: out[r, c] = split(in[c, r] * scale)
// in is [cols_out, rows_out] row-major; out is [rows_out, cols_out].
__global__ __launch_bounds__(256) void wt_split(
    const float* __restrict__ in, __half* __restrict__ h,
    __half* __restrict__ l, float scale, int rows_out, int cols_out)
{
    int idx = blockIdx.x * 256 + threadIdx.x;
    if (idx >= rows_out * cols_out) return;
    int r = idx / cols_out;
    int c = idx % cols_out;
    float v = in[(size_t)c * rows_out + r] * scale;
    __half hf = __float2half_rn(v);
    h[idx] = hf;
    l[idx] = __float2half_rn(v - __half2float(hf));
}

// ---------------------------------------------------------------------------
// 3-phase split HMMA GEMM with PERIODIC ACCUMULATOR DRAIN:
//   C[M, N] = scale * sum_{p=0..2} A_p[M, Kd] @ B_p[N, Kd]^T + bias[N]
// fp16 operands, fp32 accumulate. The tensor-core C-accumulate path is
// effectively truncating (RZ) per mma step, so long chains develop a bias
// ~n_steps * 2^-25. Every DRAIN slabs we add the mma accumulator into a
// master fp32 register accumulator (round-to-nearest FADD) and reset it,
// bounding the chain length. CTA tile 128x128, BK=32, double-buffered
// cp.async. 8 warps as 2(m) x 4(n); warp tile 64x32 via m16n8k16.
// grid = (N/128, M/128), 256 threads.
// ---------------------------------------------------------------------------
__global__ __launch_bounds__(256) void hmma_gemm3(
    const __half* __restrict__ A0, const __half* __restrict__ A1,
    const __half* __restrict__ A2,
    const __half* __restrict__ B0, const __half* __restrict__ B1,
    const __half* __restrict__ B2,
    const float* __restrict__ bias, float* __restrict__ C,
    int Kdim, int Ncols, float scale)
{
    // [buf][ A: 128 rows x 64B | B: 128 rows x 64B ]
    __shared__ __align__(16) unsigned char sm[2][16384];

    const int tid  = threadIdx.x;
    const int lane = tid & 31;
    const int wid  = tid >> 5;
    const int wm = (wid >> 2) * 64;     // warp m offset (0 / 64)
    const int wn = (wid & 3) * 32;      // warp n offset (0..96)
    const size_t arow0 = (size_t)blockIdx.y * 128;
    const size_t bcol0 = (size_t)blockIdx.x * 128;

    const __half* Alist[3] = {A0, A1, A2};
    const __half* Blist[3] = {B0, B1, B2};
    const int ns    = Kdim / 32;
    const int total = 3 * ns;

    float acc[4][4][4];     // short-chain mma accumulator
    float mst[4][4][4];     // master fp32 accumulator (RN adds)
#pragma unroll
    for (int i = 0; i < 4; i++)
#pragma unroll
        for (int j = 0; j < 4; j++)
#pragma unroll
            for (int r = 0; r < 4; r++) { acc[i][j][r] = 0.0f; mst[i][j][r] = 0.0f; }

    // --- slab loader: 128x32 fp16 A tile + B tile, swizzled 16B chunks ---
    auto load_slab = [&](int s, int buf) {
        const int ph = s / ns;
        const int k0 = (s - ph * ns) * 32;
        const __half* Ab = Alist[ph] + arow0 * Kdim + k0;
        const __half* Bb = Blist[ph] + bcol0 * Kdim + k0;
        const uint32_t sA = smem_u32(&sm[buf][0]);
        const uint32_t sB = sA + 8192;
#pragma unroll
        for (int t = 0; t < 2; t++) {
            const int idx = tid + t * 256;          // 0..511
            const int row = idx >> 2;
            const int c   = idx & 3;
            const uint32_t off = row * 64 + ((c ^ (row & 3)) * 16);
            cp_async16(sA + off, Ab + (size_t)row * Kdim + c * 8);
            cp_async16(sB + off, Bb + (size_t)row * Kdim + c * 8);
        }
        CP_COMMIT();
    };

    load_slab(0, 0);

    for (int s = 0; s < total; s++) {
        if (s + 1 < total) {
            load_slab(s + 1, (s + 1) & 1);
            CP_WAIT(1);
        } else {
            CP_WAIT(0);
        }
        __syncthreads();

        const uint32_t sA = smem_u32(&sm[s & 1][0]);
        const uint32_t sB = sA + 8192;
        const int rl = (lane & 7) + ((lane >> 3) & 1) * 8;  // row-in-16 for ldmatrix

#pragma unroll
        for (int s16 = 0; s16 < 2; s16++) {
            const int ch = s16 * 2 + (lane >> 4);           // 16B chunk (k8 index)
            uint32_t a[4][4], b[2][4];
#pragma unroll
            for (int i = 0; i < 4; i++) {
                const int row = wm + i * 16 + rl;
                ldm_x4(a[i], sA + row * 64 + ((ch ^ (row & 3)) * 16));
            }
#pragma unroll
            for (int j = 0; j < 2; j++) {
                const int row = wn + j * 16 + rl;
                ldm_x4(b[j], sB + row * 64 + ((ch ^ (row & 3)) * 16));
            }
#pragma unroll
            for (int i = 0; i < 4; i++)
#pragma unroll
                for (int nn = 0; nn < 4; nn++) {
                    const uint32_t bb0 = (nn & 1) ? b[nn >> 1][1] : b[nn >> 1][0];
                    const uint32_t bb1 = (nn & 1) ? b[nn >> 1][3] : b[nn >> 1][2];
                    mma16816(acc[i][nn], a[i], bb0, bb1);
                }
        }

        // Drain every 4 slabs (8 mma k-steps): master += acc (RN), acc = 0.
        if (((s & 3) == 3) || (s + 1 == total)) {
#pragma unroll
            for (int i = 0; i < 4; i++)
#pragma unroll
                for (int j = 0; j < 4; j++)
#pragma unroll
                    for (int r = 0; r < 4; r++) {
                        mst[i][j][r] += acc[i][j][r];
                        acc[i][j][r] = 0.0f;
                    }
        }
        __syncthreads();
    }

    // --- epilogue: scale + bias from master accumulator, float2 stores ---
    const int mrow  = lane >> 2;
    const int ncol2 = (lane & 3) * 2;
#pragma unroll
    for (int nn = 0; nn < 4; nn++) {
        const int n = (int)bcol0 + wn + nn * 8 + ncol2;
        const float2 bv = *(const float2*)(bias + n);
#pragma unroll
        for (int i = 0; i < 4; i++) {
            const size_t m0 = arow0 + wm + i * 16 + mrow;
            float2 o0, o1;
            o0.x = mst[i][nn][0] * scale + bv.x;
            o0.y = mst[i][nn][1] * scale + bv.y;
            o1.x = mst[i][nn][2] * scale + bv.x;
            o1.y = mst[i][nn][3] * scale + bv.y;
            *(float2*)(C + m0 * Ncols + n)       = o0;
            *(float2*)(C + (m0 + 8) * Ncols + n) = o1;
        }
    }
}

// ---------------------------------------------------------------------------
// Row-wise squared norms for [rows, 256] fp32. One warp per row.
// ---------------------------------------------------------------------------
__global__ void rownorm256(const float* __restrict__ src, float* __restrict__ dst,
                           int rows)
{
    const int gw   = (blockIdx.x * blockDim.x + threadIdx.x) >> 5;
    const int lane = threadIdx.x & 31;
    if (gw >= rows) return;
    const float4* p = (const float4*)(src + (size_t)gw * 256);
    float4 a = p[lane];
    float4 b = p[lane + 32];
    float s = a.x * a.x + a.y * a.y + a.z * a.z + a.w * a.w
            + b.x * b.x + b.y * b.y + b.z * b.z + b.w * b.w;
#pragma unroll
    for (int o = 16; o > 0; o >>= 1) s += __shfl_xor_sync(0xffffffffu, s, o);
    if (lane == 0) dst[gw] = s;
}

// ---------------------------------------------------------------------------
// Fused dist + stable softmin + weighted_dist. fp32 (precision-critical).
// Block: 64 emb rows x 256 clusters, 256 threads. Static smem only (41 KB);
// the [256,64] transposed result is staged+stored in two 128-row halves.
// ---------------------------------------------------------------------------
__global__ __launch_bounds__(256) void kmeans_softmin(
    const float* __restrict__ emb, const float* __restrict__ CR,
    const float* __restrict__ enorm, const float* __restrict__ cnorm,
    float* __restrict__ outWD)
{
    __shared__ float smbuf[32 * 65 + 32 * 257];   // 41216 B
    float* Es = smbuf;                  // [32][65]
    float* Cs = smbuf + 32 * 65;        // [32][257]

    const int tid  = threadIdx.x;
    const int lane = tid & 31;
    const int wid  = tid >> 5;
    const int b0   = blockIdx.x * 64;

    float acc[8][8];
#pragma unroll
    for (int i = 0; i < 8; i++)
#pragma unroll
        for (int c = 0; c < 8; c++) acc[i][c] = 0.0f;

    for (int j0 = 0; j0 < 256; j0 += 32) {
#pragma unroll
        for (int t = 0; t < 2; t++) {
            const int idx = tid + t * 256;
            const int r   = idx >> 3;
            const int c4  = idx & 7;
            float4 v = *(const float4*)(emb + (size_t)(b0 + r) * 256 + j0 + c4 * 4);
            Es[(c4 * 4 + 0) * 65 + r] = v.x;
            Es[(c4 * 4 + 1) * 65 + r] = v.y;
            Es[(c4 * 4 + 2) * 65 + r] = v.z;
            Es[(c4 * 4 + 3) * 65 + r] = v.w;
        }
#pragma unroll
        for (int t = 0; t < 8; t++) {
            const int idx = tid + t * 256;
            const int k   = idx >> 3;
            const int c4  = idx & 7;
            float4 v = *(const float4*)(CR + (size_t)k * 256 + j0 + c4 * 4);
            Cs[(c4 * 4 + 0) * 257 + k] = v.x;
            Cs[(c4 * 4 + 1) * 257 + k] = v.y;
            Cs[(c4 * 4 + 2) * 257 + k] = v.z;
            Cs[(c4 * 4 + 3) * 257 + k] = v.w;
        }
        __syncthreads();

#pragma unroll 8
        for (int kk = 0; kk < 32; kk++) {
            float ra[8], rb[8];
#pragma unroll
            for (int i = 0; i < 8; i++) ra[i] = Es[kk * 65 + wid * 8 + i];
#pragma unroll
            for (int c = 0; c < 8; c++) rb[c] = Cs[kk * 257 + lane + 32 * c];
#pragma unroll
            for (int i = 0; i < 8; i++)
#pragma unroll
                for (int c = 0; c < 8; c++)
                    acc[i][c] = fmaf(ra[i], rb[c], acc[i][c]);
        }
        __syncthreads();
    }

    float cn[8];
#pragma unroll
    for (int c = 0; c < 8; c++) cn[c] = cnorm[lane + 32 * c];

    // softmin per row; overwrite acc[i][c] with weighted_dist
#pragma unroll
    for (int i = 0; i < 8; i++) {
        const float en = enorm[b0 + wid * 8 + i];
        float dd[8];
        float m = INFINITY;
#pragma unroll
        for (int c = 0; c < 8; c++) {
            dd[c] = en - 2.0f * acc[i][c] + cn[c];
            m = fminf(m, dd[c]);
        }
#pragma unroll
        for (int o = 16; o > 0; o >>= 1)
            m = fminf(m, __shfl_xor_sync(0xffffffffu, m, o));

        float e[8];
        float s = 0.0f;
#pragma unroll
        for (int c = 0; c < 8; c++) {
            e[c] = expf(-ALPHA_ * (dd[c] - m));
            s += e[c];
        }
#pragma unroll
        for (int o = 16; o > 0; o >>= 1)
            s += __shfl_xor_sync(0xffffffffu, s, o);
        const float inv = 1.0f / s;
#pragma unroll
        for (int c = 0; c < 8; c++)
            acc[i][c] = dd[c] * e[c] * inv;
    }

    // stage + coalesced store in two 128-k-row halves (stage = [128][65])
    float* stage = smbuf;
#pragma unroll
    for (int hh = 0; hh < 2; hh++) {
        __syncthreads();
#pragma unroll
        for (int i = 0; i < 8; i++)
#pragma unroll
            for (int cc = 0; cc < 4; cc++) {
                const int c = hh * 4 + cc;
                stage[(lane + 32 * c - 128 * hh) * 65 + wid * 8 + i] = acc[i][c];
            }
        __syncthreads();
#pragma unroll
        for (int t = 0; t < 8; t++) {
            const int idx = tid + t * 256;      // 0..2047
            const int k   = idx >> 4;           // 0..127
            const int c4  = idx & 15;
            float4 o;
            o.x = stage[k * 65 + c4 * 4 + 0];
            o.y = stage[k * 65 + c4 * 4 + 1];
            o.z = stage[k * 65 + c4 * 4 + 2];
            o.w = stage[k * 65 + c4 * 4 + 3];
            *(float4*)(outWD + (size_t)(128 * hh + k) * B_ + b0 + c4 * 4) = o;
        }
    }
}

// ---------------------------------------------------------------------------
// Launch
// ---------------------------------------------------------------------------
extern "C" void kernel_launch(void* const* d_in, const int* in_sizes, int n_in,
                              void* d_out, int out_size)
{
    const float* x     = (const float*)d_in[0];  // [B, D]
    const float* W_enc = (const float*)d_in[1];  // [D, K]
    const float* b_enc = (const float*)d_in[2];  // [K]
    const float* W_dec = (const float*)d_in[3];  // [K, D]
    const float* b_dec = (const float*)d_in[4];  // [D]
    const float* CR    = (const float*)d_in[5];  // [K, K]

    float* out    = (float*)d_out;
    float* outWD  = out;                         // [K, B]
    float* outRec = out + (size_t)K_ * B_;       // [B, D]

    float *emb, *en, *cn;
    __half *xh, *xl, *weh, *wel, *wdh, *wdl, *eh, *el;
    cudaGetSymbolAddress((void**)&emb, g_emb);
    cudaGetSymbolAddress((void**)&en,  g_enorm);
    cudaGetSymbolAddress((void**)&cn,  g_cnorm);
    cudaGetSymbolAddress((void**)&xh,  g_xh);
    cudaGetSymbolAddress((void**)&xl,  g_xl);
    cudaGetSymbolAddress((void**)&weh, g_weh);
    cudaGetSymbolAddress((void**)&wel, g_wel);
    cudaGetSymbolAddress((void**)&wdh, g_wdh);
    cudaGetSymbolAddress((void**)&wdl, g_wdl);
    cudaGetSymbolAddress((void**)&eh,  g_eh);
    cudaGetSymbolAddress((void**)&el,  g_el);

    // 1) fp16 2-level splits (weights transposed + exponent pre-scaled)
    split2h<<<(B_ * D_ / 4 + 255) / 256, 256>>>(x, xh, xl, B_ * D_ / 4);
    wt_split<<<(K_ * D_ + 255) / 256, 256>>>(W_enc, weh, wel, 64.0f, K_, D_);
    wt_split<<<(D_ * K_ + 255) / 256, 256>>>(W_dec, wdh, wdl, 16.0f, D_, K_);

    // 2) emb = x @ W_enc + b_enc   (3 HMMA products: hh + hl + lh, /64)
    hmma_gemm3<<<dim3(K_ / 128, B_ / 128), 256>>>(
        xh, xh, xl, weh, wel, weh, b_enc, emb, D_, K_, 1.0f / 64.0f);

    // 3) norms
    rownorm256<<<B_ / 8, 256>>>(emb, en, B_);
    rownorm256<<<K_ / 8, 256>>>(CR, cn, K_);

    // 4) emb split; recon = emb @ W_dec + b_dec   (3 products, /16)
    split2h<<<(B_ * K_ / 4 + 255) / 256, 256>>>(emb, eh, el, B_ * K_ / 4);
    hmma_gemm3<<<dim3(D_ / 128, B_ / 128), 256>>>(
        eh, eh, el, wdh, wdl, wdh, b_dec, outRec, K_, D_, 1.0f / 16.0f);

    // 5) dist + softmin + weighted_dist
    kmeans_softmin<<<B_ / 64, 256>>>(emb, CR, en, cn, outWD);
}